// round 5
// baseline (speedup 1.0000x reference)
#include <cuda_runtime.h>
#include <cstdint>
#include <cstddef>

#define NN 100000
#define NE 1600000

// ---------------- scratch (device globals; no allocation allowed) ----------------
static __device__ float  g_y[(size_t)NN * 384];     // per-tap transformed features (max [N,3,128])
static __device__ float  g_h1[(size_t)NN * 128];    // h1 accumulator; later reused for z [N,64]
static __device__ float  g_h2[(size_t)NN * 64];     // h2
static __device__ float  g_muv[(size_t)NN * 128];   // mu|logvar accumulator; later decoder hidden
static __device__ float4 g_ew[NE];                  // {c0,c1,c2, src-as-int-bits}
static __device__ int    g_edst[NE];
static __device__ int    g_deg[NN];
static __device__ float  g_dinv[NN];
static __device__ float  g_w1T[64 * 384];           // [in=64][k*128+o]
static __device__ float  g_w2T[128 * 192];          // [in=128][k*64+o]
static __device__ float  g_w3T[64 * 384];           // [in=64][k*128 + (mu:0..63 | logvar:64..127)]
static __device__ int    g_is64;                    // edge_index dtype flag

// ---------------- small utility kernels ----------------
__global__ void k_zero(float* p, size_t n) {
    size_t i  = (size_t)blockIdx.x * blockDim.x + threadIdx.x;
    size_t st = (size_t)gridDim.x * blockDim.x;
    for (; i < n; i += st) p[i] = 0.0f;
}

// Detect whether edge_index is stored as int64 (odd 32-bit words all zero) or int32.
// Deterministic: same input -> same flag. One block of 256 threads.
__global__ void k_detect(const int* __restrict__ ei32) {
    __shared__ int any;
    if (threadIdx.x == 0) any = 0;
    __syncthreads();
    if (ei32[2 * threadIdx.x + 1] != 0) atomicOr(&any, 1);
    __syncthreads();
    if (threadIdx.x == 0) g_is64 = (any == 0) ? 1 : 0;
}

// transpose spline weights into GEMM-friendly [in][k*out+o] layouts
__global__ void k_wtrans(const float* __restrict__ w1, const float* __restrict__ w2,
                         const float* __restrict__ mw, const float* __restrict__ lw) {
    int idx = blockIdx.x * blockDim.x + threadIdx.x;
    if (idx < 3 * 64 * 128) {   // w1 [3][64][128]
        int k = idx / (64 * 128); int r = idx % (64 * 128); int i = r / 128; int o = r % 128;
        g_w1T[i * 384 + k * 128 + o] = w1[idx];
    }
    if (idx < 3 * 128 * 64) {   // w2 [3][128][64]
        int k = idx / (128 * 64); int r = idx % (128 * 64); int i = r / 64; int o = r % 64;
        g_w2T[i * 192 + k * 64 + o] = w2[idx];
    }
    if (idx < 3 * 64 * 64) {    // mu_w / logvar_w [3][64][64] fused
        int k = idx / (64 * 64); int r = idx % (64 * 64); int i = r / 64; int o = r % 64;
        g_w3T[i * 384 + k * 128 + o]      = mw[idx];
        g_w3T[i * 384 + k * 128 + 64 + o] = lw[idx];
    }
}

// per-edge: B-spline basis -> per-tap coefficients, pack {c0,c1,c2,src}, count degrees
__global__ void k_edge(const void* __restrict__ eiv, const float* __restrict__ pseudo) {
    int e = blockIdx.x * blockDim.x + threadIdx.x;
    if (e >= NE) return;
    int s, d;
    if (g_is64) {
        const long long* ei = (const long long*)eiv;
        s = (int)ei[e];
        d = (int)ei[(size_t)NE + e];
    } else {
        const int* ei = (const int*)eiv;
        s = ei[e];
        d = ei[NE + e];
    }
    // safety clamp: convert any surprise into a wrong answer, not a crash
    s = min(max(s, 0), NN - 1);
    d = min(max(d, 0), NN - 1);
    float p  = pseudo[e];
    float v  = p * 3.0f;
    float fl = floorf(v);
    float f  = v - fl;
    int bot  = ((int)fl) % 3;
    float b0 = 0.5f * f * f - f + 0.5f;
    float b1 = -f * f + f + 0.5f;
    float b2 = 0.5f * f * f;
    // coefficient for tap k is basis[s'] where (bot+s')%3 == k
    float c0, c1, c2;
    if (bot == 0)      { c0 = b0; c1 = b1; c2 = b2; }
    else if (bot == 1) { c0 = b2; c1 = b0; c2 = b1; }
    else               { c0 = b1; c1 = b2; c2 = b0; }
    g_ew[e]   = make_float4(c0, c1, c2, __int_as_float(s));
    g_edst[e] = d;
    atomicAdd(&g_deg[d], 1);
}

__global__ void k_dinv() {
    int n = blockIdx.x * blockDim.x + threadIdx.x;
    if (n < NN) g_dinv[n] = 1.0f / fmaxf((float)g_deg[n], 1.0f);
}

__global__ void k_scale(float* __restrict__ p, int shift, size_t n) {
    size_t i  = (size_t)blockIdx.x * blockDim.x + threadIdx.x;
    size_t st = (size_t)gridDim.x * blockDim.x;
    for (; i < n; i += st) p[i] *= g_dinv[i >> shift];
}

// ---------------- edge gather + atomic scatter ----------------
// out channels = 128: one warp per edge, each lane owns one float4 of channels.
__global__ void k_scat128(const float* __restrict__ y, float* __restrict__ out) {
    int lane = threadIdx.x & 31;
    int w    = (blockIdx.x * blockDim.x + threadIdx.x) >> 5;
    int nw   = (gridDim.x * blockDim.x) >> 5;
    for (int e = w; e < NE; e += nw) {
        float4 cw = g_ew[e];
        int src = __float_as_int(cw.w);
        int dst = g_edst[e];
        const float4* yr = reinterpret_cast<const float4*>(y + (size_t)src * 384);
        float4 t0 = yr[lane];
        float4 t1 = yr[32 + lane];
        float4 t2 = yr[64 + lane];
        float mx = cw.x * t0.x + cw.y * t1.x + cw.z * t2.x;
        float my = cw.x * t0.y + cw.y * t1.y + cw.z * t2.y;
        float mz = cw.x * t0.z + cw.y * t1.z + cw.z * t2.z;
        float mw = cw.x * t0.w + cw.y * t1.w + cw.z * t2.w;
        float* o = out + (size_t)dst * 128 + lane * 4;
        asm volatile("red.global.add.v4.f32 [%0], {%1,%2,%3,%4};"
                     :: "l"(o), "f"(mx), "f"(my), "f"(mz), "f"(mw) : "memory");
    }
}

// out channels = 64: half-warp per edge (2 edges per warp)
__global__ void k_scat64(const float* __restrict__ y, float* __restrict__ out) {
    int sub = threadIdx.x & 15;
    int h   = (blockIdx.x * blockDim.x + threadIdx.x) >> 4;
    int nh  = (gridDim.x * blockDim.x) >> 4;
    for (int e = h; e < NE; e += nh) {
        float4 cw = g_ew[e];
        int src = __float_as_int(cw.w);
        int dst = g_edst[e];
        const float4* yr = reinterpret_cast<const float4*>(y + (size_t)src * 192);
        float4 t0 = yr[sub];
        float4 t1 = yr[16 + sub];
        float4 t2 = yr[32 + sub];
        float mx = cw.x * t0.x + cw.y * t1.x + cw.z * t2.x;
        float my = cw.x * t0.y + cw.y * t1.y + cw.z * t2.y;
        float mz = cw.x * t0.z + cw.y * t1.z + cw.z * t2.z;
        float mw = cw.x * t0.w + cw.y * t1.w + cw.z * t2.w;
        float* o = out + (size_t)dst * 64 + sub * 4;
        asm volatile("red.global.add.v4.f32 [%0], {%1,%2,%3,%4};"
                     :: "l"(o), "f"(mx), "f"(my), "f"(mz), "f"(mw) : "memory");
    }
}

// normalize mu/logvar, write to d_out, compute z = mu + eps*exp(0.5*logvar) into g_h1
__global__ void k_final(const float* __restrict__ eps, float* __restrict__ out) {
    size_t i  = (size_t)blockIdx.x * blockDim.x + threadIdx.x;
    size_t st = (size_t)gridDim.x * blockDim.x;
    const size_t n64 = (size_t)NN * 64;
    for (; i < n64; i += st) {
        int n = (int)(i >> 6);
        int c = (int)(i & 63);
        float di = g_dinv[n];
        float mu = g_muv[((size_t)n << 7) + c] * di;
        float lv = g_muv[((size_t)n << 7) + 64 + c] * di;
        out[n64 + i]     = mu;
        out[2 * n64 + i] = lv;
        g_h1[i] = mu + eps[i] * expf(0.5f * lv);
    }
}

// ---------------- generic tiled fp32 GEMM: C[M,NC] = A[M,K] @ B[K,NC] (+bias)(+relu) ----------------
// 64x64 tile, 256 threads, 4x4 microtile, K chunked by 64. epi: 0 none, 1 bias+relu, 2 bias.
__global__ void k_gemm(const float* __restrict__ A, const float* __restrict__ B,
                       const float* __restrict__ bias, float* __restrict__ C,
                       int M, int K, int NC, int epi) {
    __shared__ float4 As4[64 * 16];
    __shared__ float4 Bs4[64 * 16];
    const float* As = reinterpret_cast<const float*>(As4);

    int tid = threadIdx.x;
    int tx  = tid & 15;
    int ty  = tid >> 4;
    int m0  = blockIdx.x * 64;
    int n0  = blockIdx.y * 64;

    float acc[4][4];
#pragma unroll
    for (int r = 0; r < 4; r++)
#pragma unroll
        for (int c = 0; c < 4; c++) acc[r][c] = 0.0f;

    for (int kc = 0; kc < K; kc += 64) {
#pragma unroll
        for (int j = 0; j < 4; j++) {
            int slot = tid + j * 256;
            int row  = slot >> 4;
            int q    = slot & 15;
            float4 av = make_float4(0.f, 0.f, 0.f, 0.f);
            if (m0 + row < M)
                av = *reinterpret_cast<const float4*>(A + (size_t)(m0 + row) * K + kc + q * 4);
            As4[slot] = av;
            Bs4[slot] = *reinterpret_cast<const float4*>(B + (size_t)(kc + row) * NC + n0 + q * 4);
        }
        __syncthreads();
#pragma unroll 16
        for (int k = 0; k < 64; k++) {
            float4 b = Bs4[k * 16 + tx];
#pragma unroll
            for (int r = 0; r < 4; r++) {
                float a = As[(ty * 4 + r) * 64 + k];
                acc[r][0] += a * b.x;
                acc[r][1] += a * b.y;
                acc[r][2] += a * b.z;
                acc[r][3] += a * b.w;
            }
        }
        __syncthreads();
    }

    float4 bv = make_float4(0.f, 0.f, 0.f, 0.f);
    if (epi) bv = *reinterpret_cast<const float4*>(bias + n0 + tx * 4);
#pragma unroll
    for (int r = 0; r < 4; r++) {
        int m = m0 + ty * 4 + r;
        if (m < M) {
            float4 o;
            o.x = acc[r][0] + bv.x;
            o.y = acc[r][1] + bv.y;
            o.z = acc[r][2] + bv.z;
            o.w = acc[r][3] + bv.w;
            if (epi == 1) {
                o.x = fmaxf(o.x, 0.f); o.y = fmaxf(o.y, 0.f);
                o.z = fmaxf(o.z, 0.f); o.w = fmaxf(o.w, 0.f);
            }
            *reinterpret_cast<float4*>(C + (size_t)m * NC + n0 + tx * 4) = o;
        }
    }
}

// ---------------- launch ----------------
extern "C" void kernel_launch(void* const* d_in, const int* in_sizes, int n_in,
                              void* d_out, int out_size) {
    const float* x      = (const float*)d_in[0];
    const float* pseudo = (const float*)d_in[1];
    const float* w1     = (const float*)d_in[2];
    const float* w2     = (const float*)d_in[3];
    const float* mu_w   = (const float*)d_in[4];
    const float* lv_w   = (const float*)d_in[5];
    const float* d1_w   = (const float*)d_in[6];
    const float* d1_b   = (const float*)d_in[7];
    const float* d2_w   = (const float*)d_in[8];
    const float* d2_b   = (const float*)d_in[9];
    const float* eps    = (const float*)d_in[10];
    const void*  ei     = d_in[11];                  // int32 (JAX default) or int64; detected on device
    float*       out    = (float*)d_out;

    float *py, *ph1, *ph2, *pmuv, *pdeg;
    float *pw1T, *pw2T, *pw3T;
    cudaGetSymbolAddress((void**)&py,   g_y);
    cudaGetSymbolAddress((void**)&ph1,  g_h1);
    cudaGetSymbolAddress((void**)&ph2,  g_h2);
    cudaGetSymbolAddress((void**)&pmuv, g_muv);
    cudaGetSymbolAddress((void**)&pw1T, g_w1T);
    cudaGetSymbolAddress((void**)&pw2T, g_w2T);
    cudaGetSymbolAddress((void**)&pw3T, g_w3T);
    cudaGetSymbolAddress((void**)&pdeg, g_deg);

    const int MB = (NN + 63) / 64;

    // edge preprocessing + degrees
    k_detect<<<1, 256>>>((const int*)ei);
    k_wtrans<<<(3 * 64 * 128 + 255) / 256, 256>>>(w1, w2, mu_w, lv_w);
    k_zero<<<256, 256>>>(pdeg, (size_t)NN);                   // zero int degrees (bit pattern 0)
    k_edge<<<(NE + 255) / 256, 256>>>(ei, pseudo);
    k_dinv<<<(NN + 255) / 256, 256>>>();

    // layer 1: h1 = sconv(x, w1)  (out=128)
    k_gemm<<<dim3(MB, 384 / 64), 256>>>(x, pw1T, nullptr, py, NN, 64, 384, 0);
    k_zero<<<512, 256>>>(ph1, (size_t)NN * 128);
    k_scat128<<<4096, 256>>>(py, ph1);
    k_scale<<<512, 256>>>(ph1, 7, (size_t)NN * 128);

    // layer 2: h2 = sconv(h1, w2)  (out=64)
    k_gemm<<<dim3(MB, 192 / 64), 256>>>(ph1, pw2T, nullptr, py, NN, 128, 192, 0);
    k_zero<<<512, 256>>>(ph2, (size_t)NN * 64);
    k_scat64<<<4096, 256>>>(py, ph2);
    k_scale<<<512, 256>>>(ph2, 6, (size_t)NN * 64);

    // layer 3+4 fused: [mu | logvar] = sconv(h2, [mu_w | logvar_w])  (out=128)
    k_gemm<<<dim3(MB, 384 / 64), 256>>>(ph2, pw3T, nullptr, py, NN, 64, 384, 0);
    k_zero<<<512, 256>>>(pmuv, (size_t)NN * 128);
    k_scat128<<<4096, 256>>>(py, pmuv);

    // normalize + write mu/logvar + reparameterize (z -> g_h1)
    k_final<<<2048, 256>>>(eps, out);

    // decoder: rec = relu(z @ d1_w + d1_b) @ d2_w + d2_b
    k_gemm<<<dim3(MB, 128 / 64), 256>>>(ph1, d1_w, d1_b, pmuv, NN, 64, 128, 1);
    k_gemm<<<dim3(MB, 64 / 64), 256>>>(pmuv, d2_w, d2_b, out, NN, 128, 64, 2);
}

// round 6
// speedup vs baseline: 1.4887x; 1.4887x over previous
#include <cuda_runtime.h>
#include <cstdint>
#include <cstddef>

#define NN 100000
#define NE 1600000

// ---------------- scratch (device globals) ----------------
static __device__ float  g_y[(size_t)NN * 384];     // t buffers [N, K*in] (max 384) / decoder hidden
static __device__ float  g_h1[(size_t)NN * 128];    // h1
static __device__ float  g_h2[(size_t)NN * 64];     // h2; later z
static __device__ float  g_muv[(size_t)NN * 128];   // mu|logvar (normalized)
static __device__ float4 g_ecsr[NE];                // CSR-ordered {c0,c1,c2, src-as-bits}
static __device__ int    g_off[NN + 1];             // CSR row offsets
static __device__ int    g_cur[NN];                 // placement cursors
static __device__ int    g_deg[NN];
static __device__ float  g_dinv[NN];
static __device__ float  g_w3T[192 * 128];          // [k*64+i][mu 0..63 | logvar 64..127]
static __device__ int    g_is64;

// ---------------- utility ----------------
__global__ void k_zero(float* p, size_t n) {
    size_t i  = (size_t)blockIdx.x * blockDim.x + threadIdx.x;
    size_t st = (size_t)gridDim.x * blockDim.x;
    for (; i < n; i += st) p[i] = 0.0f;
}

// int64 vs int32 edge_index detection (JAX default x32 delivers int32)
__global__ void k_detect(const int* __restrict__ ei32) {
    __shared__ int any;
    if (threadIdx.x == 0) any = 0;
    __syncthreads();
    if (ei32[2 * threadIdx.x + 1] != 0) atomicOr(&any, 1);
    __syncthreads();
    if (threadIdx.x == 0) g_is64 = (any == 0) ? 1 : 0;
}

__global__ void k_w3(const float* __restrict__ mw, const float* __restrict__ lw) {
    int idx = blockIdx.x * blockDim.x + threadIdx.x;
    if (idx >= 3 * 64 * 64) return;
    int o = idx & 63;
    int r = idx >> 6;              // r = k*64+i
    g_w3T[r * 128 + o]      = mw[idx];
    g_w3T[r * 128 + 64 + o] = lw[idx];
}

__device__ __forceinline__ int load_idx(const void* eiv, size_t pos) {
    if (g_is64) return (int)((const long long*)eiv)[pos];
    return ((const int*)eiv)[pos];
}

// pass 1: degree count
__global__ void k_deg(const void* __restrict__ eiv) {
    int e = blockIdx.x * blockDim.x + threadIdx.x;
    if (e >= NE) return;
    int d = load_idx(eiv, (size_t)NE + e);
    d = min(max(d, 0), NN - 1);
    atomicAdd(&g_deg[d], 1);
}

// single-block exclusive scan of g_deg -> g_off, g_cur  (1024 threads)
__global__ void k_scan() {
    __shared__ int wsum[32];
    __shared__ int carry;
    int tid = threadIdx.x, lane = tid & 31, wid = tid >> 5;
    if (tid == 0) carry = 0;
    __syncthreads();
    for (int base = 0; base < NN; base += 1024) {
        int i = base + tid;
        int v = (i < NN) ? g_deg[i] : 0;
        int incl = v;
#pragma unroll
        for (int o = 1; o < 32; o <<= 1) {
            int t = __shfl_up_sync(0xFFFFFFFFu, incl, o);
            if (lane >= o) incl += t;
        }
        if (lane == 31) wsum[wid] = incl;
        __syncthreads();
        if (wid == 0) {
            int s = wsum[lane];
            int si = s;
#pragma unroll
            for (int o = 1; o < 32; o <<= 1) {
                int t = __shfl_up_sync(0xFFFFFFFFu, si, o);
                if (lane >= o) si += t;
            }
            wsum[lane] = si - s;   // exclusive warp offsets
        }
        __syncthreads();
        int excl = carry + wsum[wid] + incl - v;
        if (i < NN) { g_off[i] = excl; g_cur[i] = excl; }
        __syncthreads();
        if (tid == 1023) carry += wsum[31] + incl;
        __syncthreads();
    }
    if (threadIdx.x == 0) g_off[NN] = carry;
}

// pass 2: compute basis coefficients, place edge meta into CSR slot
__global__ void k_place(const void* __restrict__ eiv, const float* __restrict__ pseudo) {
    int e = blockIdx.x * blockDim.x + threadIdx.x;
    if (e >= NE) return;
    int s = load_idx(eiv, e);
    int d = load_idx(eiv, (size_t)NE + e);
    s = min(max(s, 0), NN - 1);
    d = min(max(d, 0), NN - 1);
    float p  = pseudo[e];
    float v  = p * 3.0f;
    float fl = floorf(v);
    float f  = v - fl;
    int bot  = ((int)fl) % 3;
    float b0 = 0.5f * f * f - f + 0.5f;
    float b1 = -f * f + f + 0.5f;
    float b2 = 0.5f * f * f;
    float c0, c1, c2;
    if (bot == 0)      { c0 = b0; c1 = b1; c2 = b2; }
    else if (bot == 1) { c0 = b2; c1 = b0; c2 = b1; }
    else               { c0 = b1; c1 = b2; c2 = b0; }
    int pos = atomicAdd(&g_cur[d], 1);
    g_ecsr[pos] = make_float4(c0, c1, c2, __int_as_float(s));
}

__global__ void k_dinv() {
    int n = blockIdx.x * blockDim.x + threadIdx.x;
    if (n < NN) g_dinv[n] = 1.0f / fmaxf((float)g_deg[n], 1.0f);
}

// ---------------- CSR in-domain aggregation (no atomics) ----------------
// in=64: half-warp per dst. t[dst, k*64 + i] = sum_e c_k[e] * h[src[e], i] (optionally * dinv[src])
__global__ void k_agg64(const float* __restrict__ h, float* __restrict__ t, int scaleSrc) {
    int lane = threadIdx.x & 15;
    int dst  = (blockIdx.x * blockDim.x + threadIdx.x) >> 4;
    if (dst >= NN) return;
    int beg = g_off[dst], end = g_off[dst + 1];
    float4 a0 = make_float4(0.f, 0.f, 0.f, 0.f), a1 = a0, a2 = a0;
    for (int p = beg; p < end; p++) {
        float4 m = g_ecsr[p];
        int src = __float_as_int(m.w);
        float4 v = *reinterpret_cast<const float4*>(h + (size_t)src * 64 + lane * 4);
        if (scaleSrc) {
            float di = g_dinv[src];
            v.x *= di; v.y *= di; v.z *= di; v.w *= di;
        }
        a0.x += m.x * v.x; a0.y += m.x * v.y; a0.z += m.x * v.z; a0.w += m.x * v.w;
        a1.x += m.y * v.x; a1.y += m.y * v.y; a1.z += m.y * v.z; a1.w += m.y * v.w;
        a2.x += m.z * v.x; a2.y += m.z * v.y; a2.z += m.z * v.z; a2.w += m.z * v.w;
    }
    float4* tr = reinterpret_cast<float4*>(t + (size_t)dst * 192);
    tr[lane] = a0; tr[16 + lane] = a1; tr[32 + lane] = a2;
}

// in=128: full warp per dst. t[dst, k*128 + i]
__global__ void k_agg128(const float* __restrict__ h, float* __restrict__ t) {
    int lane = threadIdx.x & 31;
    int dst  = (blockIdx.x * blockDim.x + threadIdx.x) >> 5;
    if (dst >= NN) return;
    int beg = g_off[dst], end = g_off[dst + 1];
    float4 a0 = make_float4(0.f, 0.f, 0.f, 0.f), a1 = a0, a2 = a0;
    for (int p = beg; p < end; p++) {
        float4 m = g_ecsr[p];
        int src = __float_as_int(m.w);
        float4 v = *reinterpret_cast<const float4*>(h + (size_t)src * 128 + lane * 4);
        a0.x += m.x * v.x; a0.y += m.x * v.y; a0.z += m.x * v.z; a0.w += m.x * v.w;
        a1.x += m.y * v.x; a1.y += m.y * v.y; a1.z += m.y * v.z; a1.w += m.y * v.w;
        a2.x += m.z * v.x; a2.y += m.z * v.y; a2.z += m.z * v.z; a2.w += m.z * v.w;
    }
    float4* tr = reinterpret_cast<float4*>(t + (size_t)dst * 384);
    tr[lane] = a0; tr[32 + lane] = a1; tr[64 + lane] = a2;
}

// write mu/logvar to out, z = mu + eps*exp(0.5*logvar) -> g_h2
__global__ void k_final(const float* __restrict__ eps, float* __restrict__ out) {
    size_t i  = (size_t)blockIdx.x * blockDim.x + threadIdx.x;
    size_t st = (size_t)gridDim.x * blockDim.x;
    const size_t n64 = (size_t)NN * 64;
    for (; i < n64; i += st) {
        int n = (int)(i >> 6);
        int c = (int)(i & 63);
        float mu = g_muv[((size_t)n << 7) + c];
        float lv = g_muv[((size_t)n << 7) + 64 + c];
        out[n64 + i]     = mu;
        out[2 * n64 + i] = lv;
        g_h2[i] = mu + eps[i] * expf(0.5f * lv);
    }
}

// ---------------- GEMM: C[M,TN] = A[M,K] @ B[K,TN], TM=128, TK=32 ----------------
// epi: 0 none, 1 bias+relu, 2 bias, 3 row-scale by g_dinv[m]
template <int TN>
__global__ __launch_bounds__(256) void k_gemm2(
    const float* __restrict__ A, const float* __restrict__ B,
    const float* __restrict__ bias, float* __restrict__ C, int M, int K, int epi) {
    constexpr int TM = 128, TK = 32;
    constexpr int NCOL = TN / 16;       // 4 or 8 cols per thread
    __shared__ float As[TK * 132];      // [k][m], stride 132 (16B aligned)
    __shared__ float Bs[TK * TN];       // [k][n]

    int tid = threadIdx.x;
    int tx  = tid & 15;
    int ty  = tid >> 4;
    int m0  = blockIdx.x * TM;

    float acc[8][NCOL];
#pragma unroll
    for (int r = 0; r < 8; r++)
#pragma unroll
        for (int c = 0; c < NCOL; c++) acc[r][c] = 0.0f;

    for (int kc = 0; kc < K; kc += TK) {
        // A: 128 rows x 32 k, coalesced scalar loads, transposed store
#pragma unroll
        for (int i = 0; i < 16; i++) {
            int idx = tid + i * 256;
            int k = idx & 31;
            int m = idx >> 5;
            float v = 0.0f;
            int gm = m0 + m;
            if (gm < M) v = A[(size_t)gm * K + kc + k];
            As[k * 132 + m] = v;
        }
        // B: TK x TN float4 loads
#pragma unroll
        for (int i = 0; i < TK * TN / 1024; i++) {
            int idx = tid + i * 256;              // float4 slot
            int q  = idx % (TN / 4);
            int kr = idx / (TN / 4);
            *reinterpret_cast<float4*>(&Bs[kr * TN + q * 4]) =
                *reinterpret_cast<const float4*>(&B[(size_t)(kc + kr) * TN + q * 4]);
        }
        __syncthreads();
#pragma unroll 8
        for (int k = 0; k < TK; k++) {
            float4 a0 = *reinterpret_cast<const float4*>(&As[k * 132 + ty * 8]);
            float4 a1 = *reinterpret_cast<const float4*>(&As[k * 132 + ty * 8 + 4]);
            float am[8] = {a0.x, a0.y, a0.z, a0.w, a1.x, a1.y, a1.z, a1.w};
            float4 b0 = *reinterpret_cast<const float4*>(&Bs[k * TN + tx * 4]);
#pragma unroll
            for (int r = 0; r < 8; r++) {
                acc[r][0] += am[r] * b0.x;
                acc[r][1] += am[r] * b0.y;
                acc[r][2] += am[r] * b0.z;
                acc[r][3] += am[r] * b0.w;
            }
            if (TN == 128) {
                float4 b1 = *reinterpret_cast<const float4*>(&Bs[k * TN + 64 + tx * 4]);
#pragma unroll
                for (int r = 0; r < 8; r++) {
                    acc[r][NCOL - 4] += am[r] * b1.x;
                    acc[r][NCOL - 3] += am[r] * b1.y;
                    acc[r][NCOL - 2] += am[r] * b1.z;
                    acc[r][NCOL - 1] += am[r] * b1.w;
                }
            }
        }
        __syncthreads();
    }

    float4 bv0 = make_float4(0.f, 0.f, 0.f, 0.f), bv1 = bv0;
    if (epi == 1 || epi == 2) {
        bv0 = *reinterpret_cast<const float4*>(&bias[tx * 4]);
        if (TN == 128) bv1 = *reinterpret_cast<const float4*>(&bias[64 + tx * 4]);
    }
#pragma unroll
    for (int r = 0; r < 8; r++) {
        int m = m0 + ty * 8 + r;
        if (m >= M) continue;
        float rs = (epi == 3) ? g_dinv[m] : 1.0f;
        float4 o;
        o.x = (acc[r][0] + bv0.x) * rs;
        o.y = (acc[r][1] + bv0.y) * rs;
        o.z = (acc[r][2] + bv0.z) * rs;
        o.w = (acc[r][3] + bv0.w) * rs;
        if (epi == 1) {
            o.x = fmaxf(o.x, 0.f); o.y = fmaxf(o.y, 0.f);
            o.z = fmaxf(o.z, 0.f); o.w = fmaxf(o.w, 0.f);
        }
        *reinterpret_cast<float4*>(&C[(size_t)m * TN + tx * 4]) = o;
        if (TN == 128) {
            float4 p;
            p.x = (acc[r][NCOL - 4] + bv1.x) * rs;
            p.y = (acc[r][NCOL - 3] + bv1.y) * rs;
            p.z = (acc[r][NCOL - 2] + bv1.z) * rs;
            p.w = (acc[r][NCOL - 1] + bv1.w) * rs;
            if (epi == 1) {
                p.x = fmaxf(p.x, 0.f); p.y = fmaxf(p.y, 0.f);
                p.z = fmaxf(p.z, 0.f); p.w = fmaxf(p.w, 0.f);
            }
            *reinterpret_cast<float4*>(&C[(size_t)m * TN + 64 + tx * 4]) = p;
        }
    }
}

// ---------------- launch ----------------
extern "C" void kernel_launch(void* const* d_in, const int* in_sizes, int n_in,
                              void* d_out, int out_size) {
    const float* x      = (const float*)d_in[0];
    const float* pseudo = (const float*)d_in[1];
    const float* w1     = (const float*)d_in[2];   // [3][64][128] == W1cat [192][128]
    const float* w2     = (const float*)d_in[3];   // [3][128][64] == W2cat [384][64]
    const float* mu_w   = (const float*)d_in[4];
    const float* lv_w   = (const float*)d_in[5];
    const float* d1_w   = (const float*)d_in[6];   // [64][128]
    const float* d1_b   = (const float*)d_in[7];
    const float* d2_w   = (const float*)d_in[8];   // [128][64]
    const float* d2_b   = (const float*)d_in[9];
    const float* eps    = (const float*)d_in[10];
    const void*  ei     = d_in[11];
    float*       out    = (float*)d_out;

    float *py, *ph1, *ph2, *pmuv, *pw3T, *pdeg;
    cudaGetSymbolAddress((void**)&py,   g_y);
    cudaGetSymbolAddress((void**)&ph1,  g_h1);
    cudaGetSymbolAddress((void**)&ph2,  g_h2);
    cudaGetSymbolAddress((void**)&pmuv, g_muv);
    cudaGetSymbolAddress((void**)&pw3T, g_w3T);
    cudaGetSymbolAddress((void**)&pdeg, g_deg);

    const int GB = (NN + 127) / 128;   // GEMM blocks

    // --- edge preprocessing: degrees -> CSR offsets -> placement ---
    k_detect<<<1, 256>>>((const int*)ei);
    k_w3<<<(3 * 64 * 64 + 255) / 256, 256>>>(mu_w, lv_w);
    k_zero<<<256, 256>>>((float*)pdeg, (size_t)NN);
    k_deg<<<(NE + 255) / 256, 256>>>(ei);
    k_scan<<<1, 1024>>>();
    k_place<<<(NE + 255) / 256, 256>>>(ei, pseudo);
    k_dinv<<<(NN + 255) / 256, 256>>>();

    // --- layer 1: t1 = agg(x); h1 = (t1 @ w1) * dinv ---
    k_agg64<<<(NN * 16 + 255) / 256, 256>>>(x, py, 0);
    k_gemm2<128><<<GB, 256>>>(py, w1, nullptr, ph1, NN, 192, 3);

    // --- layer 2: t2 = agg(h1); h2raw = (t2 @ w2) * dinv ---
    k_agg128<<<(NN * 32 + 255) / 256, 256>>>(ph1, py);
    k_gemm2<64><<<GB, 256>>>(py, w2, nullptr, ph2, NN, 384, 3);

    // --- layer 3+4: t3 = agg(h2) ; [mu|lv] = (t3 @ w3cat) * dinv ---
    k_agg64<<<(NN * 16 + 255) / 256, 256>>>(ph2, py, 0);
    k_gemm2<128><<<GB, 256>>>(py, pw3T, nullptr, pmuv, NN, 192, 3);

    // mu/logvar out + reparameterize (z -> g_h2)
    k_final<<<2048, 256>>>(eps, out);

    // decoder
    k_gemm2<128><<<GB, 256>>>(ph2, d1_w, d1_b, py, NN, 64, 1);
    k_gemm2<64><<<GB, 256>>>(py, d2_w, d2_b, out, NN, 128, 2);
}

// round 7
// speedup vs baseline: 1.6509x; 1.1090x over previous
#include <cuda_runtime.h>
#include <cstdint>
#include <cstddef>

#define NN 100000
#define NE 1600000
#define SCAN_B ((NN + 255) / 256)   // 391

// ---------------- scratch (device globals) ----------------
static __device__ float  g_y[(size_t)NN * 384];     // t buffers [N, K*in] (max 384) / decoder hidden
static __device__ float  g_h1[(size_t)NN * 128];    // h1
static __device__ float  g_h2[(size_t)NN * 64];     // h2; later z
static __device__ float  g_muv[(size_t)NN * 128];   // mu|logvar (normalized)
static __device__ float4 g_ecsr[NE];                // CSR-ordered {c0,c1,c2, src-as-bits}
static __device__ int    g_off[NN + 1];             // CSR row offsets
static __device__ int    g_cur[NN];                 // placement cursors
static __device__ int    g_deg[NN];
static __device__ float  g_dinv[NN];
static __device__ float  g_w3T[192 * 128];          // [k*64+i][mu 0..63 | logvar 64..127]
static __device__ int    g_bsum[512];
static __device__ int    g_boff[512];
static __device__ int    g_is64;

// ---------------- utility ----------------
__global__ void k_zero(float* p, size_t n) {
    size_t i  = (size_t)blockIdx.x * blockDim.x + threadIdx.x;
    size_t st = (size_t)gridDim.x * blockDim.x;
    for (; i < n; i += st) p[i] = 0.0f;
}

// int64 vs int32 edge_index detection (JAX default x32 delivers int32)
__global__ void k_detect(const int* __restrict__ ei32) {
    __shared__ int any;
    if (threadIdx.x == 0) any = 0;
    __syncthreads();
    if (ei32[2 * threadIdx.x + 1] != 0) atomicOr(&any, 1);
    __syncthreads();
    if (threadIdx.x == 0) g_is64 = (any == 0) ? 1 : 0;
}

__global__ void k_w3(const float* __restrict__ mw, const float* __restrict__ lw) {
    int idx = blockIdx.x * blockDim.x + threadIdx.x;
    if (idx >= 3 * 64 * 64) return;
    int o = idx & 63;
    int r = idx >> 6;              // r = k*64+i
    g_w3T[r * 128 + o]      = mw[idx];
    g_w3T[r * 128 + 64 + o] = lw[idx];
}

__device__ __forceinline__ int load_idx(const void* eiv, size_t pos) {
    if (g_is64) return (int)((const long long*)eiv)[pos];
    return ((const int*)eiv)[pos];
}

// pass 1: degree count
__global__ void k_deg(const void* __restrict__ eiv) {
    int e = blockIdx.x * blockDim.x + threadIdx.x;
    if (e >= NE) return;
    int d = load_idx(eiv, (size_t)NE + e);
    d = min(max(d, 0), NN - 1);
    atomicAdd(&g_deg[d], 1);
}

// ---------------- two-level scan ----------------
// level 1: per-block (256) sums
__global__ void k_scan1() {
    __shared__ int ws[8];
    int i = blockIdx.x * 256 + threadIdx.x;
    int lane = threadIdx.x & 31, wid = threadIdx.x >> 5;
    int v = (i < NN) ? g_deg[i] : 0;
    int s = v;
#pragma unroll
    for (int o = 1; o < 32; o <<= 1) {
        int t = __shfl_up_sync(0xFFFFFFFFu, s, o);
        if (lane >= o) s += t;
    }
    if (lane == 31) ws[wid] = s;
    __syncthreads();
    if (threadIdx.x == 0) {
        int tot = 0;
#pragma unroll
        for (int w = 0; w < 8; w++) tot += ws[w];
        g_bsum[blockIdx.x] = tot;
    }
}

// level 2: exclusive scan of SCAN_B block sums (1 block, 512 threads)
__global__ void k_scan2() {
    __shared__ int ws[16];
    int tid = threadIdx.x, lane = tid & 31, wid = tid >> 5;
    int v = (tid < SCAN_B) ? g_bsum[tid] : 0;
    int s = v;
#pragma unroll
    for (int o = 1; o < 32; o <<= 1) {
        int t = __shfl_up_sync(0xFFFFFFFFu, s, o);
        if (lane >= o) s += t;
    }
    if (lane == 31) ws[wid] = s;
    __syncthreads();
    if (wid == 0 && lane < 16) {
        int a = ws[lane];
        int si = a;
#pragma unroll
        for (int o = 1; o < 16; o <<= 1) {
            int t = __shfl_up_sync(0xFFFFu, si, o);
            if (lane >= o) si += t;
        }
        ws[lane] = si - a;
    }
    __syncthreads();
    int incl = ws[wid] + s;
    if (tid < SCAN_B) g_boff[tid] = incl - v;
    if (tid == SCAN_B - 1) g_off[NN] = incl;
}

// level 3: in-block exclusive scan + block offset; also dinv + cursors
__global__ void k_scan3() {
    __shared__ int ws[8];
    int i = blockIdx.x * 256 + threadIdx.x;
    int lane = threadIdx.x & 31, wid = threadIdx.x >> 5;
    int v = (i < NN) ? g_deg[i] : 0;
    int s = v;
#pragma unroll
    for (int o = 1; o < 32; o <<= 1) {
        int t = __shfl_up_sync(0xFFFFFFFFu, s, o);
        if (lane >= o) s += t;
    }
    if (lane == 31) ws[wid] = s;
    __syncthreads();
    if (wid == 0 && lane < 8) {
        int a = ws[lane];
        int si = a;
#pragma unroll
        for (int o = 1; o < 8; o <<= 1) {
            int t = __shfl_up_sync(0xFFu, si, o);
            if (lane >= o) si += t;
        }
        ws[lane] = si - a;
    }
    __syncthreads();
    if (i < NN) {
        int excl = g_boff[blockIdx.x] + ws[wid] + s - v;
        g_off[i] = excl;
        g_cur[i] = excl;
        g_dinv[i] = 1.0f / fmaxf((float)v, 1.0f);
    }
}

// pass 2: compute basis coefficients, place edge meta into CSR slot
__global__ void k_place(const void* __restrict__ eiv, const float* __restrict__ pseudo) {
    int e = blockIdx.x * blockDim.x + threadIdx.x;
    if (e >= NE) return;
    int s = load_idx(eiv, e);
    int d = load_idx(eiv, (size_t)NE + e);
    s = min(max(s, 0), NN - 1);
    d = min(max(d, 0), NN - 1);
    float p  = pseudo[e];
    float v  = p * 3.0f;
    float fl = floorf(v);
    float f  = v - fl;
    int bot  = ((int)fl) % 3;
    float b0 = 0.5f * f * f - f + 0.5f;
    float b1 = -f * f + f + 0.5f;
    float b2 = 0.5f * f * f;
    float c0, c1, c2;
    if (bot == 0)      { c0 = b0; c1 = b1; c2 = b2; }
    else if (bot == 1) { c0 = b2; c1 = b0; c2 = b1; }
    else               { c0 = b1; c1 = b2; c2 = b0; }
    int pos = atomicAdd(&g_cur[d], 1);
    g_ecsr[pos] = make_float4(c0, c1, c2, __int_as_float(s));
}

// ---------------- CSR in-domain aggregation (no atomics) ----------------
// in=64: half-warp per dst. t[dst, k*64 + i] = sum_e c_k[e] * h[src[e], i]
__global__ void k_agg64(const float* __restrict__ h, float* __restrict__ t) {
    int lane = threadIdx.x & 15;
    int dst  = (blockIdx.x * blockDim.x + threadIdx.x) >> 4;
    if (dst >= NN) return;
    int beg = g_off[dst], end = g_off[dst + 1];
    float4 a0 = make_float4(0.f, 0.f, 0.f, 0.f), a1 = a0, a2 = a0;
    for (int p = beg; p < end; p++) {
        float4 m = g_ecsr[p];
        int src = __float_as_int(m.w);
        float4 v = *reinterpret_cast<const float4*>(h + (size_t)src * 64 + lane * 4);
        a0.x += m.x * v.x; a0.y += m.x * v.y; a0.z += m.x * v.z; a0.w += m.x * v.w;
        a1.x += m.y * v.x; a1.y += m.y * v.y; a1.z += m.y * v.z; a1.w += m.y * v.w;
        a2.x += m.z * v.x; a2.y += m.z * v.y; a2.z += m.z * v.z; a2.w += m.z * v.w;
    }
    float4* tr = reinterpret_cast<float4*>(t + (size_t)dst * 192);
    tr[lane] = a0; tr[16 + lane] = a1; tr[32 + lane] = a2;
}

// in=128: full warp per dst. t[dst, k*128 + i]
__global__ void k_agg128(const float* __restrict__ h, float* __restrict__ t) {
    int lane = threadIdx.x & 31;
    int dst  = (blockIdx.x * blockDim.x + threadIdx.x) >> 5;
    if (dst >= NN) return;
    int beg = g_off[dst], end = g_off[dst + 1];
    float4 a0 = make_float4(0.f, 0.f, 0.f, 0.f), a1 = a0, a2 = a0;
    for (int p = beg; p < end; p++) {
        float4 m = g_ecsr[p];
        int src = __float_as_int(m.w);
        float4 v = *reinterpret_cast<const float4*>(h + (size_t)src * 128 + lane * 4);
        a0.x += m.x * v.x; a0.y += m.x * v.y; a0.z += m.x * v.z; a0.w += m.x * v.w;
        a1.x += m.y * v.x; a1.y += m.y * v.y; a1.z += m.y * v.z; a1.w += m.y * v.w;
        a2.x += m.z * v.x; a2.y += m.z * v.y; a2.z += m.z * v.z; a2.w += m.z * v.w;
    }
    float4* tr = reinterpret_cast<float4*>(t + (size_t)dst * 384);
    tr[lane] = a0; tr[32 + lane] = a1; tr[64 + lane] = a2;
}

// write mu/logvar to out, z = mu + eps*exp(0.5*logvar) -> g_h2
__global__ void k_final(const float* __restrict__ eps, float* __restrict__ out) {
    size_t i  = (size_t)blockIdx.x * blockDim.x + threadIdx.x;
    size_t st = (size_t)gridDim.x * blockDim.x;
    const size_t n64 = (size_t)NN * 64;
    for (; i < n64; i += st) {
        int n = (int)(i >> 6);
        int c = (int)(i & 63);
        float mu = g_muv[((size_t)n << 7) + c];
        float lv = g_muv[((size_t)n << 7) + 64 + c];
        out[n64 + i]     = mu;
        out[2 * n64 + i] = lv;
        g_h2[i] = mu + eps[i] * expf(0.5f * lv);
    }
}

// ---------------- GEMM with packed f32x2 math ----------------
// C[M,TN] = A[M,K] @ B[K,TN], TM=128, TK=32, 256 threads, 8 rows x TN/16 cols per thread.
// epi: 0 none, 1 bias+relu, 2 bias, 3 row-scale by g_dinv[m]
typedef unsigned long long ull;

template <int TN>
__global__ __launch_bounds__(256) void k_gemm2(
    const float* __restrict__ A, const float* __restrict__ B,
    const float* __restrict__ bias, float* __restrict__ C, int M, int K, int epi) {
    constexpr int TM = 128, TK = 32;
    constexpr int NPAIR = TN / 32;      // packed f32x2 accumulators per row: 2 or 4
    __shared__ float As[TK * 132];      // [k][m], stride 132 (16B aligned)
    __shared__ float Bs[TK * TN];       // [k][n]

    int tid = threadIdx.x;
    int tx  = tid & 15;
    int ty  = tid >> 4;
    int m0  = blockIdx.x * TM;

    ull acc[8][NPAIR];
#pragma unroll
    for (int r = 0; r < 8; r++)
#pragma unroll
        for (int c = 0; c < NPAIR; c++) acc[r][c] = 0ull;

    for (int kc = 0; kc < K; kc += TK) {
        // A: 128 rows x 32 k, coalesced scalar loads, transposed store
#pragma unroll
        for (int i = 0; i < 16; i++) {
            int idx = tid + i * 256;
            int k = idx & 31;
            int m = idx >> 5;
            float v = 0.0f;
            int gm = m0 + m;
            if (gm < M) v = A[(size_t)gm * K + kc + k];
            As[k * 132 + m] = v;
        }
        // B: TK x TN float4 loads
#pragma unroll
        for (int i = 0; i < TK * TN / 1024; i++) {
            int idx = tid + i * 256;              // float4 slot
            int q  = idx % (TN / 4);
            int kr = idx / (TN / 4);
            *reinterpret_cast<float4*>(&Bs[kr * TN + q * 4]) =
                *reinterpret_cast<const float4*>(&B[(size_t)(kc + kr) * TN + q * 4]);
        }
        __syncthreads();
#pragma unroll 8
        for (int k = 0; k < TK; k++) {
            float4 a0 = *reinterpret_cast<const float4*>(&As[k * 132 + ty * 8]);
            float4 a1 = *reinterpret_cast<const float4*>(&As[k * 132 + ty * 8 + 4]);
            float am[8] = {a0.x, a0.y, a0.z, a0.w, a1.x, a1.y, a1.z, a1.w};
            ull ap[8];
#pragma unroll
            for (int r = 0; r < 8; r++)
                asm("mov.b64 %0, {%1, %1};" : "=l"(ap[r]) : "f"(am[r]));
            ulonglong2 b0 = *reinterpret_cast<const ulonglong2*>(&Bs[k * TN + tx * 4]);
#pragma unroll
            for (int r = 0; r < 8; r++) {
                asm("fma.rn.f32x2 %0, %1, %2, %0;" : "+l"(acc[r][0]) : "l"(ap[r]), "l"(b0.x));
                asm("fma.rn.f32x2 %0, %1, %2, %0;" : "+l"(acc[r][1]) : "l"(ap[r]), "l"(b0.y));
            }
            if (TN == 128) {
                ulonglong2 b1 = *reinterpret_cast<const ulonglong2*>(&Bs[k * TN + 64 + tx * 4]);
#pragma unroll
                for (int r = 0; r < 8; r++) {
                    asm("fma.rn.f32x2 %0, %1, %2, %0;" : "+l"(acc[r][NPAIR - 2]) : "l"(ap[r]), "l"(b1.x));
                    asm("fma.rn.f32x2 %0, %1, %2, %0;" : "+l"(acc[r][NPAIR - 1]) : "l"(ap[r]), "l"(b1.y));
                }
            }
        }
        __syncthreads();
    }

    float4 bv0 = make_float4(0.f, 0.f, 0.f, 0.f), bv1 = bv0;
    if (epi == 1 || epi == 2) {
        bv0 = *reinterpret_cast<const float4*>(&bias[tx * 4]);
        if (TN == 128) bv1 = *reinterpret_cast<const float4*>(&bias[64 + tx * 4]);
    }
#pragma unroll
    for (int r = 0; r < 8; r++) {
        int m = m0 + ty * 8 + r;
        if (m >= M) continue;
        float rs = (epi == 3) ? g_dinv[m] : 1.0f;
        float f0, f1, f2, f3;
        asm("mov.b64 {%0, %1}, %2;" : "=f"(f0), "=f"(f1) : "l"(acc[r][0]));
        asm("mov.b64 {%0, %1}, %2;" : "=f"(f2), "=f"(f3) : "l"(acc[r][1]));
        float4 o;
        o.x = (f0 + bv0.x) * rs;
        o.y = (f1 + bv0.y) * rs;
        o.z = (f2 + bv0.z) * rs;
        o.w = (f3 + bv0.w) * rs;
        if (epi == 1) {
            o.x = fmaxf(o.x, 0.f); o.y = fmaxf(o.y, 0.f);
            o.z = fmaxf(o.z, 0.f); o.w = fmaxf(o.w, 0.f);
        }
        *reinterpret_cast<float4*>(&C[(size_t)m * TN + tx * 4]) = o;
        if (TN == 128) {
            asm("mov.b64 {%0, %1}, %2;" : "=f"(f0), "=f"(f1) : "l"(acc[r][NPAIR - 2]));
            asm("mov.b64 {%0, %1}, %2;" : "=f"(f2), "=f"(f3) : "l"(acc[r][NPAIR - 1]));
            float4 p;
            p.x = (f0 + bv1.x) * rs;
            p.y = (f1 + bv1.y) * rs;
            p.z = (f2 + bv1.z) * rs;
            p.w = (f3 + bv1.w) * rs;
            if (epi == 1) {
                p.x = fmaxf(p.x, 0.f); p.y = fmaxf(p.y, 0.f);
                p.z = fmaxf(p.z, 0.f); p.w = fmaxf(p.w, 0.f);
            }
            *reinterpret_cast<float4*>(&C[(size_t)m * TN + 64 + tx * 4]) = p;
        }
    }
}

// ---------------- launch ----------------
extern "C" void kernel_launch(void* const* d_in, const int* in_sizes, int n_in,
                              void* d_out, int out_size) {
    const float* x      = (const float*)d_in[0];
    const float* pseudo = (const float*)d_in[1];
    const float* w1     = (const float*)d_in[2];   // [3][64][128] == W1cat [192][128]
    const float* w2     = (const float*)d_in[3];   // [3][128][64] == W2cat [384][64]
    const float* mu_w   = (const float*)d_in[4];
    const float* lv_w   = (const float*)d_in[5];
    const float* d1_w   = (const float*)d_in[6];   // [64][128]
    const float* d1_b   = (const float*)d_in[7];
    const float* d2_w   = (const float*)d_in[8];   // [128][64]
    const float* d2_b   = (const float*)d_in[9];
    const float* eps    = (const float*)d_in[10];
    const void*  ei     = d_in[11];
    float*       out    = (float*)d_out;

    float *py, *ph1, *ph2, *pmuv, *pw3T, *pdeg;
    cudaGetSymbolAddress((void**)&py,   g_y);
    cudaGetSymbolAddress((void**)&ph1,  g_h1);
    cudaGetSymbolAddress((void**)&ph2,  g_h2);
    cudaGetSymbolAddress((void**)&pmuv, g_muv);
    cudaGetSymbolAddress((void**)&pw3T, g_w3T);
    cudaGetSymbolAddress((void**)&pdeg, g_deg);

    const int GB = (NN + 127) / 128;   // GEMM blocks

    // --- edge preprocessing: degrees -> CSR offsets -> placement ---
    k_detect<<<1, 256>>>((const int*)ei);
    k_w3<<<(3 * 64 * 64 + 255) / 256, 256>>>(mu_w, lv_w);
    k_zero<<<256, 256>>>((float*)pdeg, (size_t)NN);
    k_deg<<<(NE + 255) / 256, 256>>>(ei);
    k_scan1<<<SCAN_B, 256>>>();
    k_scan2<<<1, 512>>>();
    k_scan3<<<SCAN_B, 256>>>();
    k_place<<<(NE + 255) / 256, 256>>>(ei, pseudo);

    // --- layer 1: t1 = agg(x); h1 = (t1 @ w1) * dinv ---
    k_agg64<<<(NN * 16 + 255) / 256, 256>>>(x, py);
    k_gemm2<128><<<GB, 256>>>(py, w1, nullptr, ph1, NN, 192, 3);

    // --- layer 2: t2 = agg(h1); h2 = (t2 @ w2) * dinv ---
    k_agg128<<<(NN * 32 + 255) / 256, 256>>>(ph1, py);
    k_gemm2<64><<<GB, 256>>>(py, w2, nullptr, ph2, NN, 384, 3);

    // --- layer 3+4: t3 = agg(h2); [mu|lv] = (t3 @ w3cat) * dinv ---
    k_agg64<<<(NN * 16 + 255) / 256, 256>>>(ph2, py);
    k_gemm2<128><<<GB, 256>>>(py, pw3T, nullptr, pmuv, NN, 192, 3);

    // mu/logvar out + reparameterize (z -> g_h2)
    k_final<<<2048, 256>>>(eps, out);

    // decoder
    k_gemm2<128><<<GB, 256>>>(ph2, d1_w, d1_b, py, NN, 64, 1);
    k_gemm2<64><<<GB, 256>>>(py, d2_w, d2_b, out, NN, 128, 2);
}

// round 8
// speedup vs baseline: 1.8862x; 1.1425x over previous
#include <cuda_runtime.h>
#include <cstdint>
#include <cstddef>

#define NN 100000
#define NE 1600000
#define SCAN_B ((NN + 255) / 256)   // 391

typedef unsigned long long ull;

// ---------------- scratch (device globals) ----------------
static __device__ float  g_y[(size_t)NN * 384];     // t buffers [N, K*in] (max 384) / decoder hidden
static __device__ float  g_h1[(size_t)NN * 128];    // h1
static __device__ float  g_h2[(size_t)NN * 64];     // h2; later z
static __device__ float4 g_ecsr[NE];                // CSR-ordered {c0,c1,c2, src-as-bits}
static __device__ int    g_off[NN + 1];             // CSR row offsets
static __device__ int    g_cur[NN];                 // placement cursors
static __device__ int    g_deg[NN];
static __device__ float  g_dinv[NN];
static __device__ float  g_w3T[192 * 128];          // [k*64+i][mu 0..63 | logvar 64..127]
static __device__ int    g_bsum[512];
static __device__ int    g_boff[512];
static __device__ int    g_is64;

// ---------------- fused prep: dtype detect + w3 interleave + zero degrees ----------------
__global__ void k_prep(const int* __restrict__ ei32, const float* __restrict__ mw,
                       const float* __restrict__ lw) {
    int idx = blockIdx.x * 256 + threadIdx.x;
    if (blockIdx.x == 0) {
        int nz = (ei32[2 * threadIdx.x + 1] != 0) ? 1 : 0;
        int any = __syncthreads_or(nz);
        if (threadIdx.x == 0) g_is64 = any ? 0 : 1;
    }
    if (idx < 3 * 64 * 64) {
        int o = idx & 63;
        int r = idx >> 6;              // r = k*64+i
        g_w3T[r * 128 + o]      = mw[idx];
        g_w3T[r * 128 + 64 + o] = lw[idx];
    }
    if (idx < NN) g_deg[idx] = 0;
}

__device__ __forceinline__ int load_idx(const void* eiv, size_t pos) {
    if (g_is64) return (int)((const long long*)eiv)[pos];
    return ((const int*)eiv)[pos];
}

// pass 1: degree count
__global__ void k_deg(const void* __restrict__ eiv) {
    int e = blockIdx.x * blockDim.x + threadIdx.x;
    if (e >= NE) return;
    int d = load_idx(eiv, (size_t)NE + e);
    d = min(max(d, 0), NN - 1);
    atomicAdd(&g_deg[d], 1);
}

// ---------------- two-level scan ----------------
__global__ void k_scan1() {
    __shared__ int ws[8];
    int i = blockIdx.x * 256 + threadIdx.x;
    int lane = threadIdx.x & 31, wid = threadIdx.x >> 5;
    int v = (i < NN) ? g_deg[i] : 0;
    int s = v;
#pragma unroll
    for (int o = 1; o < 32; o <<= 1) {
        int t = __shfl_up_sync(0xFFFFFFFFu, s, o);
        if (lane >= o) s += t;
    }
    if (lane == 31) ws[wid] = s;
    __syncthreads();
    if (threadIdx.x == 0) {
        int tot = 0;
#pragma unroll
        for (int w = 0; w < 8; w++) tot += ws[w];
        g_bsum[blockIdx.x] = tot;
    }
}

__global__ void k_scan2() {
    __shared__ int ws[16];
    int tid = threadIdx.x, lane = tid & 31, wid = tid >> 5;
    int v = (tid < SCAN_B) ? g_bsum[tid] : 0;
    int s = v;
#pragma unroll
    for (int o = 1; o < 32; o <<= 1) {
        int t = __shfl_up_sync(0xFFFFFFFFu, s, o);
        if (lane >= o) s += t;
    }
    if (lane == 31) ws[wid] = s;
    __syncthreads();
    if (wid == 0 && lane < 16) {
        int a = ws[lane];
        int si = a;
#pragma unroll
        for (int o = 1; o < 16; o <<= 1) {
            int t = __shfl_up_sync(0xFFFFu, si, o);
            if (lane >= o) si += t;
        }
        ws[lane] = si - a;
    }
    __syncthreads();
    int incl = ws[wid] + s;
    if (tid < SCAN_B) g_boff[tid] = incl - v;
    if (tid == SCAN_B - 1) g_off[NN] = incl;
}

__global__ void k_scan3() {
    __shared__ int ws[8];
    int i = blockIdx.x * 256 + threadIdx.x;
    int lane = threadIdx.x & 31, wid = threadIdx.x >> 5;
    int v = (i < NN) ? g_deg[i] : 0;
    int s = v;
#pragma unroll
    for (int o = 1; o < 32; o <<= 1) {
        int t = __shfl_up_sync(0xFFFFFFFFu, s, o);
        if (lane >= o) s += t;
    }
    if (lane == 31) ws[wid] = s;
    __syncthreads();
    if (wid == 0 && lane < 8) {
        int a = ws[lane];
        int si = a;
#pragma unroll
        for (int o = 1; o < 8; o <<= 1) {
            int t = __shfl_up_sync(0xFFu, si, o);
            if (lane >= o) si += t;
        }
        ws[lane] = si - a;
    }
    __syncthreads();
    if (i < NN) {
        int excl = g_boff[blockIdx.x] + ws[wid] + s - v;
        g_off[i] = excl;
        g_cur[i] = excl;
        g_dinv[i] = 1.0f / fmaxf((float)v, 1.0f);
    }
}

// pass 2: basis coefficients + CSR placement
__global__ void k_place(const void* __restrict__ eiv, const float* __restrict__ pseudo) {
    int e = blockIdx.x * blockDim.x + threadIdx.x;
    if (e >= NE) return;
    int s = load_idx(eiv, e);
    int d = load_idx(eiv, (size_t)NE + e);
    s = min(max(s, 0), NN - 1);
    d = min(max(d, 0), NN - 1);
    float p  = pseudo[e];
    float v  = p * 3.0f;
    float fl = floorf(v);
    float f  = v - fl;
    int bot  = ((int)fl) % 3;
    float b0 = 0.5f * f * f - f + 0.5f;
    float b1 = -f * f + f + 0.5f;
    float b2 = 0.5f * f * f;
    float c0, c1, c2;
    if (bot == 0)      { c0 = b0; c1 = b1; c2 = b2; }
    else if (bot == 1) { c0 = b2; c1 = b0; c2 = b1; }
    else               { c0 = b1; c1 = b2; c2 = b0; }
    int pos = atomicAdd(&g_cur[d], 1);
    g_ecsr[pos] = make_float4(c0, c1, c2, __int_as_float(s));
}

// ---------------- CSR in-domain aggregation, unroll x4 for MLP ----------------
#define AGG_FMA(a0, a1, a2, m, v)                                            \
    a0.x += m.x * v.x; a0.y += m.x * v.y; a0.z += m.x * v.z; a0.w += m.x * v.w; \
    a1.x += m.y * v.x; a1.y += m.y * v.y; a1.z += m.y * v.z; a1.w += m.y * v.w; \
    a2.x += m.z * v.x; a2.y += m.z * v.y; a2.z += m.z * v.z; a2.w += m.z * v.w;

__global__ void k_agg64(const float* __restrict__ h, float* __restrict__ t) {
    int lane = threadIdx.x & 15;
    int dst  = (blockIdx.x * blockDim.x + threadIdx.x) >> 4;
    if (dst >= NN) return;
    int p = g_off[dst], end = g_off[dst + 1];
    float4 a0 = make_float4(0.f, 0.f, 0.f, 0.f), a1 = a0, a2 = a0;
    for (; p + 3 < end; p += 4) {
        float4 m0 = g_ecsr[p], m1 = g_ecsr[p + 1], m2 = g_ecsr[p + 2], m3 = g_ecsr[p + 3];
        float4 v0 = *reinterpret_cast<const float4*>(h + ((size_t)__float_as_int(m0.w)) * 64 + lane * 4);
        float4 v1 = *reinterpret_cast<const float4*>(h + ((size_t)__float_as_int(m1.w)) * 64 + lane * 4);
        float4 v2 = *reinterpret_cast<const float4*>(h + ((size_t)__float_as_int(m2.w)) * 64 + lane * 4);
        float4 v3 = *reinterpret_cast<const float4*>(h + ((size_t)__float_as_int(m3.w)) * 64 + lane * 4);
        AGG_FMA(a0, a1, a2, m0, v0)
        AGG_FMA(a0, a1, a2, m1, v1)
        AGG_FMA(a0, a1, a2, m2, v2)
        AGG_FMA(a0, a1, a2, m3, v3)
    }
    for (; p < end; p++) {
        float4 m = g_ecsr[p];
        float4 v = *reinterpret_cast<const float4*>(h + ((size_t)__float_as_int(m.w)) * 64 + lane * 4);
        AGG_FMA(a0, a1, a2, m, v)
    }
    float4* tr = reinterpret_cast<float4*>(t + (size_t)dst * 192);
    tr[lane] = a0; tr[16 + lane] = a1; tr[32 + lane] = a2;
}

__global__ void k_agg128(const float* __restrict__ h, float* __restrict__ t) {
    int lane = threadIdx.x & 31;
    int dst  = (blockIdx.x * blockDim.x + threadIdx.x) >> 5;
    if (dst >= NN) return;
    int p = g_off[dst], end = g_off[dst + 1];
    float4 a0 = make_float4(0.f, 0.f, 0.f, 0.f), a1 = a0, a2 = a0;
    for (; p + 3 < end; p += 4) {
        float4 m0 = g_ecsr[p], m1 = g_ecsr[p + 1], m2 = g_ecsr[p + 2], m3 = g_ecsr[p + 3];
        float4 v0 = *reinterpret_cast<const float4*>(h + ((size_t)__float_as_int(m0.w)) * 128 + lane * 4);
        float4 v1 = *reinterpret_cast<const float4*>(h + ((size_t)__float_as_int(m1.w)) * 128 + lane * 4);
        float4 v2 = *reinterpret_cast<const float4*>(h + ((size_t)__float_as_int(m2.w)) * 128 + lane * 4);
        float4 v3 = *reinterpret_cast<const float4*>(h + ((size_t)__float_as_int(m3.w)) * 128 + lane * 4);
        AGG_FMA(a0, a1, a2, m0, v0)
        AGG_FMA(a0, a1, a2, m1, v1)
        AGG_FMA(a0, a1, a2, m2, v2)
        AGG_FMA(a0, a1, a2, m3, v3)
    }
    for (; p < end; p++) {
        float4 m = g_ecsr[p];
        float4 v = *reinterpret_cast<const float4*>(h + ((size_t)__float_as_int(m.w)) * 128 + lane * 4);
        AGG_FMA(a0, a1, a2, m, v)
    }
    float4* tr = reinterpret_cast<float4*>(t + (size_t)dst * 384);
    tr[lane] = a0; tr[32 + lane] = a1; tr[64 + lane] = a2;
}

// ---------------- GEMM: packed f32x2 math + register double-buffering ----------------
// C[M,TN] = A[M,K] @ B[K,TN], TM=128, TK=32, 256 threads, 8 rows x TN/16 cols/thread.
// epi: 0 none, 1 bias+relu, 2 bias, 3 row-scale dinv, 4 fused mu/logvar/z (TN=128 only)
template <int TN>
__global__ __launch_bounds__(256, 2) void k_gemm2(
    const float* __restrict__ A, const float* __restrict__ B,
    const float* __restrict__ bias, float* __restrict__ C, int M, int K, int epi,
    const float* __restrict__ eps, float* __restrict__ outmlv, float* __restrict__ zout) {
    constexpr int TK = 32;
    constexpr int NPAIR = TN / 32;      // packed accumulators per row: 2 or 4
    constexpr int NB = TN / 32;         // B reg-buffer float4s per thread
    __shared__ float As[TK * 132];
    __shared__ float Bs[TK * TN];

    int tid = threadIdx.x;
    int tx  = tid & 15;
    int ty  = tid >> 4;
    int m0  = blockIdx.x * 128;

    float  ar[16];
    float4 br[NB];

    // load chunk 0 into registers
    {
#pragma unroll
        for (int i = 0; i < 16; i++) {
            int idx = tid + i * 256;
            int gm = m0 + (idx >> 5);
            ar[i] = (gm < M) ? A[(size_t)gm * K + (idx & 31)] : 0.0f;
        }
#pragma unroll
        for (int i = 0; i < NB; i++) {
            int idx = tid + i * 256;
            br[i] = *reinterpret_cast<const float4*>(&B[(size_t)(idx / (TN / 4)) * TN + (idx % (TN / 4)) * 4]);
        }
    }

    ull acc[8][NPAIR];
#pragma unroll
    for (int r = 0; r < 8; r++)
#pragma unroll
        for (int c = 0; c < NPAIR; c++) acc[r][c] = 0ull;

    for (int kc = 0; kc < K; kc += TK) {
        // registers -> smem
#pragma unroll
        for (int i = 0; i < 16; i++) {
            int idx = tid + i * 256;
            As[(idx & 31) * 132 + (idx >> 5)] = ar[i];
        }
#pragma unroll
        for (int i = 0; i < NB; i++) {
            int idx = tid + i * 256;
            *reinterpret_cast<float4*>(&Bs[(idx / (TN / 4)) * TN + (idx % (TN / 4)) * 4]) = br[i];
        }
        __syncthreads();
        // prefetch next chunk (hidden behind compute)
        if (kc + TK < K) {
            int kn = kc + TK;
#pragma unroll
            for (int i = 0; i < 16; i++) {
                int idx = tid + i * 256;
                int gm = m0 + (idx >> 5);
                ar[i] = (gm < M) ? A[(size_t)gm * K + kn + (idx & 31)] : 0.0f;
            }
#pragma unroll
            for (int i = 0; i < NB; i++) {
                int idx = tid + i * 256;
                br[i] = *reinterpret_cast<const float4*>(&B[(size_t)(kn + idx / (TN / 4)) * TN + (idx % (TN / 4)) * 4]);
            }
        }
#pragma unroll 8
        for (int k = 0; k < TK; k++) {
            float4 a0 = *reinterpret_cast<const float4*>(&As[k * 132 + ty * 8]);
            float4 a1 = *reinterpret_cast<const float4*>(&As[k * 132 + ty * 8 + 4]);
            float am[8] = {a0.x, a0.y, a0.z, a0.w, a1.x, a1.y, a1.z, a1.w};
            ull ap[8];
#pragma unroll
            for (int r = 0; r < 8; r++)
                asm("mov.b64 %0, {%1, %1};" : "=l"(ap[r]) : "f"(am[r]));
            ulonglong2 b0 = *reinterpret_cast<const ulonglong2*>(&Bs[k * TN + tx * 4]);
#pragma unroll
            for (int r = 0; r < 8; r++) {
                asm("fma.rn.f32x2 %0, %1, %2, %0;" : "+l"(acc[r][0]) : "l"(ap[r]), "l"(b0.x));
                asm("fma.rn.f32x2 %0, %1, %2, %0;" : "+l"(acc[r][1]) : "l"(ap[r]), "l"(b0.y));
            }
            if (TN == 128) {
                ulonglong2 b1 = *reinterpret_cast<const ulonglong2*>(&Bs[k * TN + 64 + tx * 4]);
#pragma unroll
                for (int r = 0; r < 8; r++) {
                    asm("fma.rn.f32x2 %0, %1, %2, %0;" : "+l"(acc[r][NPAIR - 2]) : "l"(ap[r]), "l"(b1.x));
                    asm("fma.rn.f32x2 %0, %1, %2, %0;" : "+l"(acc[r][NPAIR - 1]) : "l"(ap[r]), "l"(b1.y));
                }
            }
        }
        __syncthreads();
    }

    // ---------------- epilogue ----------------
    if (epi == 4) {  // fused: mu | logvar -> outmlv, z -> zout  (TN==128)
        const size_t n64 = (size_t)NN * 64;
#pragma unroll
        for (int r = 0; r < 8; r++) {
            int m = m0 + ty * 8 + r;
            if (m >= M) continue;
            float rs = g_dinv[m];
            float mu0, mu1, mu2, mu3, lv0, lv1, lv2, lv3;
            asm("mov.b64 {%0, %1}, %2;" : "=f"(mu0), "=f"(mu1) : "l"(acc[r][0]));
            asm("mov.b64 {%0, %1}, %2;" : "=f"(mu2), "=f"(mu3) : "l"(acc[r][1]));
            asm("mov.b64 {%0, %1}, %2;" : "=f"(lv0), "=f"(lv1) : "l"(acc[r][NPAIR - 2]));
            asm("mov.b64 {%0, %1}, %2;" : "=f"(lv2), "=f"(lv3) : "l"(acc[r][NPAIR - 1]));
            mu0 *= rs; mu1 *= rs; mu2 *= rs; mu3 *= rs;
            lv0 *= rs; lv1 *= rs; lv2 *= rs; lv3 *= rs;
            size_t base = (size_t)m * 64 + tx * 4;
            float4 ev = *reinterpret_cast<const float4*>(&eps[base]);
            float4 zv;
            zv.x = mu0 + ev.x * expf(0.5f * lv0);
            zv.y = mu1 + ev.y * expf(0.5f * lv1);
            zv.z = mu2 + ev.z * expf(0.5f * lv2);
            zv.w = mu3 + ev.w * expf(0.5f * lv3);
            *reinterpret_cast<float4*>(&outmlv[n64 + base])     = make_float4(mu0, mu1, mu2, mu3);
            *reinterpret_cast<float4*>(&outmlv[2 * n64 + base]) = make_float4(lv0, lv1, lv2, lv3);
            *reinterpret_cast<float4*>(&zout[base]) = zv;
        }
        return;
    }

    float4 bv0 = make_float4(0.f, 0.f, 0.f, 0.f), bv1 = bv0;
    if (epi == 1 || epi == 2) {
        bv0 = *reinterpret_cast<const float4*>(&bias[tx * 4]);
        if (TN == 128) bv1 = *reinterpret_cast<const float4*>(&bias[64 + tx * 4]);
    }
#pragma unroll
    for (int r = 0; r < 8; r++) {
        int m = m0 + ty * 8 + r;
        if (m >= M) continue;
        float rs = (epi == 3) ? g_dinv[m] : 1.0f;
        float f0, f1, f2, f3;
        asm("mov.b64 {%0, %1}, %2;" : "=f"(f0), "=f"(f1) : "l"(acc[r][0]));
        asm("mov.b64 {%0, %1}, %2;" : "=f"(f2), "=f"(f3) : "l"(acc[r][1]));
        float4 o;
        o.x = (f0 + bv0.x) * rs;
        o.y = (f1 + bv0.y) * rs;
        o.z = (f2 + bv0.z) * rs;
        o.w = (f3 + bv0.w) * rs;
        if (epi == 1) {
            o.x = fmaxf(o.x, 0.f); o.y = fmaxf(o.y, 0.f);
            o.z = fmaxf(o.z, 0.f); o.w = fmaxf(o.w, 0.f);
        }
        *reinterpret_cast<float4*>(&C[(size_t)m * TN + tx * 4]) = o;
        if (TN == 128) {
            asm("mov.b64 {%0, %1}, %2;" : "=f"(f0), "=f"(f1) : "l"(acc[r][NPAIR - 2]));
            asm("mov.b64 {%0, %1}, %2;" : "=f"(f2), "=f"(f3) : "l"(acc[r][NPAIR - 1]));
            float4 p;
            p.x = (f0 + bv1.x) * rs;
            p.y = (f1 + bv1.y) * rs;
            p.z = (f2 + bv1.z) * rs;
            p.w = (f3 + bv1.w) * rs;
            if (epi == 1) {
                p.x = fmaxf(p.x, 0.f); p.y = fmaxf(p.y, 0.f);
                p.z = fmaxf(p.z, 0.f); p.w = fmaxf(p.w, 0.f);
            }
            *reinterpret_cast<float4*>(&C[(size_t)m * TN + 64 + tx * 4]) = p;
        }
    }
}

// ---------------- launch ----------------
extern "C" void kernel_launch(void* const* d_in, const int* in_sizes, int n_in,
                              void* d_out, int out_size) {
    const float* x      = (const float*)d_in[0];
    const float* pseudo = (const float*)d_in[1];
    const float* w1     = (const float*)d_in[2];   // [3][64][128] == W1cat [192][128]
    const float* w2     = (const float*)d_in[3];   // [3][128][64] == W2cat [384][64]
    const float* mu_w   = (const float*)d_in[4];
    const float* lv_w   = (const float*)d_in[5];
    const float* d1_w   = (const float*)d_in[6];   // [64][128]
    const float* d1_b   = (const float*)d_in[7];
    const float* d2_w   = (const float*)d_in[8];   // [128][64]
    const float* d2_b   = (const float*)d_in[9];
    const float* eps    = (const float*)d_in[10];
    const void*  ei     = d_in[11];
    float*       out    = (float*)d_out;

    float *py, *ph1, *ph2, *pw3T;
    cudaGetSymbolAddress((void**)&py,   g_y);
    cudaGetSymbolAddress((void**)&ph1,  g_h1);
    cudaGetSymbolAddress((void**)&ph2,  g_h2);
    cudaGetSymbolAddress((void**)&pw3T, g_w3T);

    const int GB = (NN + 127) / 128;

    // --- edge preprocessing: degrees -> CSR offsets -> placement ---
    k_prep<<<SCAN_B, 256>>>((const int*)ei, mu_w, lv_w);
    k_deg<<<(NE + 255) / 256, 256>>>(ei);
    k_scan1<<<SCAN_B, 256>>>();
    k_scan2<<<1, 512>>>();
    k_scan3<<<SCAN_B, 256>>>();
    k_place<<<(NE + 255) / 256, 256>>>(ei, pseudo);

    // --- layer 1: t1 = agg(x); h1 = (t1 @ w1) * dinv ---
    k_agg64<<<(NN * 16 + 255) / 256, 256>>>(x, py);
    k_gemm2<128><<<GB, 256>>>(py, w1, nullptr, ph1, NN, 192, 3, nullptr, nullptr, nullptr);

    // --- layer 2: t2 = agg(h1); h2 = (t2 @ w2) * dinv ---
    k_agg128<<<(NN * 32 + 255) / 256, 256>>>(ph1, py);
    k_gemm2<64><<<GB, 256>>>(py, w2, nullptr, ph2, NN, 384, 3, nullptr, nullptr, nullptr);

    // --- layer 3+4: t3 = agg(h2); fused epilogue: mu/logvar -> out, z -> g_h2 ---
    k_agg64<<<(NN * 16 + 255) / 256, 256>>>(ph2, py);
    k_gemm2<128><<<GB, 256>>>(py, pw3T, nullptr, nullptr, NN, 192, 4, eps, out, ph2);

    // --- decoder: rec = relu(z @ d1_w + d1_b) @ d2_w + d2_b ---
    k_gemm2<128><<<GB, 256>>>(ph2, d1_w, d1_b, py, NN, 64, 1, nullptr, nullptr, nullptr);
    k_gemm2<64><<<GB, 256>>>(py, d2_w, d2_b, out, NN, 128, 2, nullptr, nullptr, nullptr);
}